// round 15
// baseline (speedup 1.0000x reference)
#include <cuda_runtime.h>

// ---------------------------------------------------------------------------
// SWMSA: shifted-window multi-head self-attention (Swin block attention)
// B=32, H=W=56, WS=7, SS=3, NH=8, E=256, HD=32, NW=64, WD=49
// Kernel A : one-shot rel-pos-bias + shift-mask tables (4 window types)
// Kernel A2: one-shot proj_w -> tf32 pre-conversion
// Kernel B : tensor-core fused QKV + attention (R8 shape, x-loads hoisted,
//            epilogue stores tf32 bits into g_O)
// Kernel C : output projection GEMM, 3-stage cp.async pipeline (wait_group 1)
// ---------------------------------------------------------------------------

#define BNUM 32
#define HW   56
#define NHEAD 8
#define EMB  256
#define HDIM 32
#define NWIN 64
#define WD   49
#define NTOK (HW*HW)              // 3136

__device__ __align__(16) float    g_O  [(size_t)BNUM*NTOK*EMB];   // tf32 bits
__device__ __align__(16) float    g_BiM[4*NHEAD*WD*WD];           // 307KB, L2
__device__ __align__(16) unsigned g_Wp [EMB*EMB];                 // tf32 bits

// ---------------------------------------------------------------------------
__device__ __forceinline__ unsigned f2tf32(float f) {
    unsigned r;
    asm("cvt.rna.tf32.f32 %0, %1;" : "=r"(r) : "f"(f));
    return r;
}

__global__ __launch_bounds__(512) void bias_kernel(const float* __restrict__ rpb) {
    int i = blockIdx.x * 512 + threadIdx.x;
    if (i >= NHEAD*WD*WD) return;
    int h  = i / (WD*WD);
    int r2 = i - h*(WD*WD);
    int a  = r2 / WD;
    int bb = r2 - a*WD;
    int atr = a/7,  atc = a - 7*atr;
    int btr = bb/7, btc = bb - 7*btr;
    float bias = rpb[((atr - btr + 6)*13 + (atc - btc + 6))*NHEAD + h];
#pragma unroll
    for (int ty = 0; ty < 4; ++ty) {
        int Rw = ty >> 1, Cw = ty & 1;
        int ra = (Rw ? (atr<4?1:2) : 0)*3 + (Cw ? (atc<4?1:2) : 0);
        int rb = (Rw ? (btr<4?1:2) : 0)*3 + (Cw ? (btc<4?1:2) : 0);
        g_BiM[ty*(NHEAD*WD*WD) + i] = bias + ((ra == rb) ? 0.f : -100.f);
    }
}

__global__ __launch_bounds__(512) void wconv_kernel(const float* __restrict__ Wp) {
    int i = blockIdx.x * 512 + threadIdx.x;
    if (i < EMB*EMB) g_Wp[i] = f2tf32(Wp[i]);
}

// ---------------------------------------------------------------------------
__device__ __forceinline__ void mma_tf32(float* c, unsigned a0, unsigned a1,
                                         unsigned a2, unsigned a3,
                                         unsigned b0, unsigned b1) {
    asm volatile(
        "mma.sync.aligned.m16n8k8.row.col.f32.tf32.tf32.f32 "
        "{%0,%1,%2,%3}, {%4,%5,%6,%7}, {%8,%9}, {%0,%1,%2,%3};\n"
        : "+f"(c[0]), "+f"(c[1]), "+f"(c[2]), "+f"(c[3])
        : "r"(a0), "r"(a1), "r"(a2), "r"(a3), "r"(b0), "r"(b1));
}

__device__ __forceinline__ void cp_async16(unsigned smem_addr, const void* gptr) {
    asm volatile("cp.async.ca.shared.global [%0], [%1], 16;\n"
                 :: "r"(smem_addr), "l"(gptr));
}
#define CP_COMMIT() asm volatile("cp.async.commit_group;\n" ::: "memory")
#define CP_WAIT1()  asm volatile("cp.async.wait_group 1;\n" ::: "memory")

// ---------------------------------------------------------------------------
// Fused kernel smem layout (floats), block = (window, 4 heads)  [R8 shape]:
//   Ks @ 0     : 4 heads x 32 d x 56 j (tf32)            = 7168
//   Vs @ 7168  : 4 heads x 32 d x 60 j (tf32, zeroed)    = 7680
//   Ws @ 14848 : 32 k x stride 104 (tf32)                = 3328
//   bs @ 18176 : 96 (fp32)
//   gof@ 18272 : 64 ints
//   total 18336 floats = 73,344 B  -> 2 blocks/SM
// ---------------------------------------------------------------------------
#define OFF_KS 0
#define KS_H   1792
#define OFF_VS 7168
#define VS_H   1920
#define OFF_WS 14848
#define WS_S   104
#define OFF_BS 18176
#define OFF_GO 18272
#define SMEM_FLOATS 18336

__global__ __launch_bounds__(256, 2) void fused_kernel(const float* __restrict__ x,
                                                       const float* __restrict__ Wq,
                                                       const float* __restrict__ bq) {
    extern __shared__ float sm[];
    float* bs  = sm + OFF_BS;
    int*   gof = reinterpret_cast<int*>(sm + OFF_GO);
    unsigned* Wsu = reinterpret_cast<unsigned*>(sm + OFF_WS);

    int bw2 = blockIdx.x;
    int hg = bw2 & 1, bw = bw2 >> 1;
    int b  = bw >> 6, w = bw & 63;
    int wr = w >> 3,  wc = w & 7;
    int tid = threadIdx.x, warp = tid >> 5, lane = tid & 31;
    int g = lane >> 2, t = lane & 3;
    int lh = warp >> 1, p = warp & 1;
    int h = hg*4 + lh;
    int m0_0 = p ? 17 : 0;
    int m0_1 = p ? 33 : 16;
    int hc = h*HDIM;

    // ---- issue A-frag loads FIRST (hidden behind staging below) ----
    auto rowoff = [&](int i) {
        int tr = i/7, tc = i - 7*tr;
        int row = wr*7 + tr + 3; if (row >= HW) row -= HW;
        int col = wc*7 + tc + 3; if (col >= HW) col -= HW;
        return (b*NTOK + row*HW + col)*EMB + hc;
    };
    float av[2][4][4];
    {
        int o00 = rowoff(m0_0 + g), o01 = rowoff(m0_0 + g + 8);
        int o10 = rowoff(m0_1 + g), o11 = rowoff(m0_1 + g + 8);
#pragma unroll
        for (int ks = 0; ks < 4; ++ks) {
            int k0 = ks*8;
            av[0][ks][0] = __ldg(x + o00 + k0 + t    );
            av[0][ks][1] = __ldg(x + o01 + k0 + t    );
            av[0][ks][2] = __ldg(x + o00 + k0 + t + 4);
            av[0][ks][3] = __ldg(x + o01 + k0 + t + 4);
            av[1][ks][0] = __ldg(x + o10 + k0 + t    );
            av[1][ks][1] = __ldg(x + o11 + k0 + t    );
            av[1][ks][2] = __ldg(x + o10 + k0 + t + 4);
            av[1][ks][3] = __ldg(x + o11 + k0 + t + 4);
        }
    }

    // ---- staging (overlaps the LDGs above) ----
    {
        float4* z = reinterpret_cast<float4*>(sm + OFF_VS);
        for (int i = tid; i < 7680/4; i += 256) z[i] = make_float4(0,0,0,0);
    }
    for (int i = tid; i < 32*96; i += 256) {
        int k = i / 96, n = i - k*96;
        Wsu[k*WS_S + n] = f2tf32(Wq[i]);
    }
    if (tid < 96) bs[tid] = bq[tid];
    if (tid < WD) {
        int tr = tid/7, tc = tid - 7*tr;
        int row = wr*7 + tr + 3; if (row >= HW) row -= HW;
        int col = wc*7 + tc + 3; if (col >= HW) col -= HW;
        gof[tid] = (b*NTOK + row*HW + col)*EMB;
    }
    __syncthreads();

    // convert A-frags to tf32
    unsigned a_[2][4][4];
#pragma unroll
    for (int mi = 0; mi < 2; ++mi)
#pragma unroll
        for (int ks = 0; ks < 4; ++ks)
#pragma unroll
            for (int i = 0; i < 4; ++i)
                a_[mi][ks][i] = f2tf32(av[mi][ks][i]);

    // ---- Q pass (cols 0..31) -> frags (scaled, tf32) ----
    unsigned qu[2][4][4];
    const float qscale = 0.17677669529663687f;
#pragma unroll
    for (int mi = 0; mi < 2; ++mi) {
#pragma unroll
        for (int nt = 0; nt < 4; ++nt) {
            float c4[4] = {0.f,0.f,0.f,0.f};
#pragma unroll
            for (int ks = 0; ks < 4; ++ks) {
                int k0 = ks*8;
                unsigned b0 = Wsu[(k0+t  )*WS_S + nt*8 + g];
                unsigned b1 = Wsu[(k0+t+4)*WS_S + nt*8 + g];
                mma_tf32(c4, a_[mi][ks][0],a_[mi][ks][1],a_[mi][ks][2],a_[mi][ks][3], b0,b1);
            }
            int d0 = nt*8 + 2*t;
            qu[mi][nt][0] = f2tf32((c4[0] + bs[d0  ]) * qscale);
            qu[mi][nt][1] = f2tf32((c4[1] + bs[d0+1]) * qscale);
            qu[mi][nt][2] = f2tf32((c4[2] + bs[d0  ]) * qscale);
            qu[mi][nt][3] = f2tf32((c4[3] + bs[d0+1]) * qscale);
        }
    }
    // ---- K pass (cols 32..63) -> Ks[d][j] stride 56 ----
    {
        unsigned* Kh = reinterpret_cast<unsigned*>(sm + OFF_KS) + lh*KS_H;
#pragma unroll
        for (int mi = 0; mi < 2; ++mi) {
            int m0 = mi ? m0_1 : m0_0;
#pragma unroll
            for (int nt = 0; nt < 4; ++nt) {
                float c4[4] = {0.f,0.f,0.f,0.f};
#pragma unroll
                for (int ks = 0; ks < 4; ++ks) {
                    int k0 = ks*8;
                    unsigned b0 = Wsu[(k0+t  )*WS_S + 32 + nt*8 + g];
                    unsigned b1 = Wsu[(k0+t+4)*WS_S + 32 + nt*8 + g];
                    mma_tf32(c4, a_[mi][ks][0],a_[mi][ks][1],a_[mi][ks][2],a_[mi][ks][3], b0,b1);
                }
                int d0 = nt*8 + 2*t;
                Kh[(d0  )*56 + m0+g  ] = f2tf32(c4[0] + bs[32+d0  ]);
                Kh[(d0+1)*56 + m0+g  ] = f2tf32(c4[1] + bs[32+d0+1]);
                Kh[(d0  )*56 + m0+g+8] = f2tf32(c4[2] + bs[32+d0  ]);
                Kh[(d0+1)*56 + m0+g+8] = f2tf32(c4[3] + bs[32+d0+1]);
            }
        }
    }
    // ---- V pass (cols 64..95) -> Vs[d][j] stride 60 (transposed) ----
    {
        unsigned* Vh = reinterpret_cast<unsigned*>(sm + OFF_VS) + lh*VS_H;
#pragma unroll
        for (int mi = 0; mi < 2; ++mi) {
            int m0 = mi ? m0_1 : m0_0;
#pragma unroll
            for (int nt = 0; nt < 4; ++nt) {
                float c4[4] = {0.f,0.f,0.f,0.f};
#pragma unroll
                for (int ks = 0; ks < 4; ++ks) {
                    int k0 = ks*8;
                    unsigned b0 = Wsu[(k0+t  )*WS_S + 64 + nt*8 + g];
                    unsigned b1 = Wsu[(k0+t+4)*WS_S + 64 + nt*8 + g];
                    mma_tf32(c4, a_[mi][ks][0],a_[mi][ks][1],a_[mi][ks][2],a_[mi][ks][3], b0,b1);
                }
                int d0 = nt*8 + 2*t;
                Vh[(d0  )*60 + m0+g  ] = f2tf32(c4[0] + bs[64+d0  ]);
                Vh[(d0+1)*60 + m0+g  ] = f2tf32(c4[1] + bs[64+d0+1]);
                Vh[(d0  )*60 + m0+g+8] = f2tf32(c4[2] + bs[64+d0  ]);
                Vh[(d0+1)*60 + m0+g+8] = f2tf32(c4[3] + bs[64+d0+1]);
            }
        }
    }

    // rearrange Q c-frags -> a-frags via warp shuffles
    int src0 = (g << 2) | (t >> 1);
    unsigned qa[2][4][4];
#pragma unroll
    for (int mi = 0; mi < 2; ++mi)
#pragma unroll
        for (int ks = 0; ks < 4; ++ks) {
            unsigned v00 = __shfl_sync(0xffffffffu, qu[mi][ks][0], src0);
            unsigned v01 = __shfl_sync(0xffffffffu, qu[mi][ks][1], src0);
            unsigned v02 = __shfl_sync(0xffffffffu, qu[mi][ks][2], src0);
            unsigned v03 = __shfl_sync(0xffffffffu, qu[mi][ks][3], src0);
            unsigned v10 = __shfl_sync(0xffffffffu, qu[mi][ks][0], src0+2);
            unsigned v11 = __shfl_sync(0xffffffffu, qu[mi][ks][1], src0+2);
            unsigned v12 = __shfl_sync(0xffffffffu, qu[mi][ks][2], src0+2);
            unsigned v13 = __shfl_sync(0xffffffffu, qu[mi][ks][3], src0+2);
            bool odd = (t & 1);
            qa[mi][ks][0] = odd ? v01 : v00;
            qa[mi][ks][1] = odd ? v03 : v02;
            qa[mi][ks][2] = odd ? v11 : v10;
            qa[mi][ks][3] = odd ? v13 : v12;
        }

    __syncthreads();

    // ---- scores: S = Q · K^T ----
    float s[2][7][4];
#pragma unroll
    for (int mi = 0; mi < 2; ++mi)
#pragma unroll
        for (int nt = 0; nt < 7; ++nt)
            s[mi][nt][0]=s[mi][nt][1]=s[mi][nt][2]=s[mi][nt][3]=0.f;
    {
        const unsigned* Kh = reinterpret_cast<const unsigned*>(sm + OFF_KS) + lh*KS_H;
#pragma unroll
        for (int ks = 0; ks < 4; ++ks) {
            int k0 = ks*8;
#pragma unroll
            for (int nt = 0; nt < 7; ++nt) {
                unsigned b0 = Kh[(k0+t  )*56 + nt*8 + g];
                unsigned b1 = Kh[(k0+t+4)*56 + nt*8 + g];
                mma_tf32(s[0][nt], qa[0][ks][0],qa[0][ks][1],qa[0][ks][2],qa[0][ks][3], b0,b1);
                mma_tf32(s[1][nt], qa[1][ks][0],qa[1][ks][1],qa[1][ks][2],qa[1][ks][3], b0,b1);
            }
        }
    }

    // ---- softmax (bias+mask precombined per window type) ----
    int ty = ((wr == 7) ? 2 : 0) + ((wc == 7) ? 1 : 0);
    const float* Bh = g_BiM + (ty*NHEAD + h)*(WD*WD);
    int row0[2] = {m0_0 + g, m0_1 + g};
    float inv_l[2][2];
#pragma unroll
    for (int mi = 0; mi < 2; ++mi) {
#pragma unroll
        for (int half = 0; half < 2; ++half) {
            int i = row0[mi] + half*8;
            const float* Br = Bh + i*WD;
            float mx = -1e30f;
#pragma unroll
            for (int nt = 0; nt < 7; ++nt) {
#pragma unroll
                for (int c = 0; c < 2; ++c) {
                    int j = nt*8 + 2*t + c;
                    float v = (j < WD) ? s[mi][nt][half*2+c] + __ldg(Br + j) : -1e30f;
                    s[mi][nt][half*2+c] = v;
                    mx = fmaxf(mx, v);
                }
            }
            mx = fmaxf(mx, __shfl_xor_sync(0xffffffffu, mx, 1));
            mx = fmaxf(mx, __shfl_xor_sync(0xffffffffu, mx, 2));
            float l = 0.f;
#pragma unroll
            for (int nt = 0; nt < 7; ++nt)
#pragma unroll
                for (int c = 0; c < 2; ++c) {
                    float e = __expf(s[mi][nt][half*2+c] - mx);
                    s[mi][nt][half*2+c] = e;
                    l += e;
                }
            l += __shfl_xor_sync(0xffffffffu, l, 1);
            l += __shfl_xor_sync(0xffffffffu, l, 2);
            inv_l[mi][half] = 1.f / l;
        }
    }
#pragma unroll
    for (int mi = 0; mi < 2; ++mi)
#pragma unroll
        for (int nt = 0; nt < 7; ++nt)
#pragma unroll
            for (int c = 0; c < 4; ++c)
                s[mi][nt][c] = __uint_as_float(f2tf32(s[mi][nt][c]));

    // ---- PV: O = P · V ----
    float o[2][4][4];
#pragma unroll
    for (int mi = 0; mi < 2; ++mi)
#pragma unroll
        for (int nt = 0; nt < 4; ++nt)
            o[mi][nt][0]=o[mi][nt][1]=o[mi][nt][2]=o[mi][nt][3]=0.f;
    {
        const unsigned* Vh = reinterpret_cast<const unsigned*>(sm + OFF_VS) + lh*VS_H;
#pragma unroll
        for (int ks = 0; ks < 7; ++ks) {
            int k0 = ks*8;
            unsigned pa[2][4];
#pragma unroll
            for (int mi = 0; mi < 2; ++mi) {
                float v00 = __shfl_sync(0xffffffffu, s[mi][ks][0], src0);
                float v01 = __shfl_sync(0xffffffffu, s[mi][ks][1], src0);
                float v02 = __shfl_sync(0xffffffffu, s[mi][ks][2], src0);
                float v03 = __shfl_sync(0xffffffffu, s[mi][ks][3], src0);
                float v10 = __shfl_sync(0xffffffffu, s[mi][ks][0], src0+2);
                float v11 = __shfl_sync(0xffffffffu, s[mi][ks][1], src0+2);
                float v12 = __shfl_sync(0xffffffffu, s[mi][ks][2], src0+2);
                float v13 = __shfl_sync(0xffffffffu, s[mi][ks][3], src0+2);
                bool odd = (t & 1);
                pa[mi][0] = __float_as_uint(odd ? v01 : v00);
                pa[mi][1] = __float_as_uint(odd ? v03 : v02);
                pa[mi][2] = __float_as_uint(odd ? v11 : v10);
                pa[mi][3] = __float_as_uint(odd ? v13 : v12);
            }
#pragma unroll
            for (int nt = 0; nt < 4; ++nt) {
                unsigned b0 = Vh[(nt*8+g)*60 + k0+t  ];
                unsigned b1 = Vh[(nt*8+g)*60 + k0+t+4];
                mma_tf32(o[0][nt], pa[0][0],pa[0][1],pa[0][2],pa[0][3], b0,b1);
                mma_tf32(o[1][nt], pa[1][0],pa[1][1],pa[1][2],pa[1][3], b0,b1);
            }
        }
    }

    // ---- scatter output as tf32 bits (exactly what proj would convert) ----
#pragma unroll
    for (int mi = 0; mi < 2; ++mi)
#pragma unroll
        for (int half = 0; half < 2; ++half) {
            int i = row0[mi] + half*8;
            float inv = inv_l[mi][half];
            float* dst = g_O + gof[i] + hc;
#pragma unroll
            for (int nt = 0; nt < 4; ++nt) {
                float2 v;
                v.x = __uint_as_float(f2tf32(o[mi][nt][half*2+0] * inv));
                v.y = __uint_as_float(f2tf32(o[mi][nt][half*2+1] * inv));
                *reinterpret_cast<float2*>(dst + nt*8 + 2*t) = v;
            }
        }
}

// ---------------------------------------------------------------------------
// Kernel C: output projection GEMM. A (g_O) and B (g_Wp) are already tf32
// bits; staging is raw cp.async copies, 3-stage pipeline, wait_group 1.
// A buffer row-major [m][k] stride 36 ((4g+t)%32 frag pattern: conflict-free).
// ---------------------------------------------------------------------------
#define PA_SZ (128*36)       // 4608 words per A buffer
#define PB_SZ (32*136)       // 4352 words per B buffer
#define PSTG  (PA_SZ + PB_SZ)               // 8960 words per stage
#define PROJ_SMEM (3*PSTG*4)                // 107,520 B

__device__ __forceinline__ void proj_stage(int kb, unsigned* Ab, unsigned* Bb,
                                           const float* Ag, const unsigned* Wg,
                                           int tid, int bn) {
    int ar = tid >> 1, ac = (tid & 1) * 16;
    unsigned ad = (unsigned)__cvta_generic_to_shared(Ab + ar*36 + ac);
    const float* asrc = Ag + ar*EMB + kb*32 + ac;
#pragma unroll
    for (int i = 0; i < 4; ++i) cp_async16(ad + i*16, asrc + i*4);
    int br = tid >> 3, bc = (tid & 7) * 16;
    unsigned bd = (unsigned)__cvta_generic_to_shared(Bb + br*136 + bc);
    const unsigned* bsrc = Wg + (kb*32 + br)*EMB + bn*128 + bc;
#pragma unroll
    for (int i = 0; i < 4; ++i) cp_async16(bd + i*16, bsrc + i*4);
}

__global__ __launch_bounds__(256) void proj_kernel(const float* __restrict__ bp,
                                                   float* __restrict__ out) {
    extern __shared__ unsigned psm[];
    unsigned* Ab[3] = {psm, psm + PSTG, psm + 2*PSTG};
    unsigned* Bb[3] = {psm + PA_SZ, psm + PSTG + PA_SZ, psm + 2*PSTG + PA_SZ};

    int bm = blockIdx.x;
    int bn = blockIdx.y;
    int tid = threadIdx.x;
    int warp = tid >> 5, lane = tid & 31;
    int g = lane >> 2, t = lane & 3;
    int wm = (warp & 1) * 64;
    int wn = (warp >> 1) * 32;

    float acc[4][4][4];
#pragma unroll
    for (int mi = 0; mi < 4; ++mi)
#pragma unroll
        for (int ni = 0; ni < 4; ++ni)
#pragma unroll
            for (int rr = 0; rr < 4; ++rr) acc[mi][ni][rr] = 0.f;

    const float* Ag = g_O + (size_t)bm * 128 * EMB;

    // prologue: two stages in flight
    proj_stage(0, Ab[0], Bb[0], Ag, g_Wp, tid, bn);
    CP_COMMIT();
    proj_stage(1, Ab[1], Bb[1], Ag, g_Wp, tid, bn);
    CP_COMMIT();

#pragma unroll 1
    for (int kb = 0; kb < 8; ++kb) {
        int cur = kb % 3;
        CP_WAIT1();            // group kb done; group kb+1 may still fly
        __syncthreads();       // also: everyone finished reading buf (kb-1 mod 3)
        if (kb + 2 < 8) {
            proj_stage(kb + 2, Ab[(kb+2)%3], Bb[(kb+2)%3], Ag, g_Wp, tid, bn);
            CP_COMMIT();
        }
        const unsigned* A_ = Ab[cur];
        const unsigned* B_ = Bb[cur];
#pragma unroll
        for (int ks = 0; ks < 4; ++ks) {
            int k0 = ks * 8;
            unsigned af[4][4];
#pragma unroll
            for (int mi = 0; mi < 4; ++mi) {
                int m0 = wm + mi*16;
                af[mi][0] = A_[(m0 + g    )*36 + k0 + t    ];
                af[mi][1] = A_[(m0 + g + 8)*36 + k0 + t    ];
                af[mi][2] = A_[(m0 + g    )*36 + k0 + t + 4];
                af[mi][3] = A_[(m0 + g + 8)*36 + k0 + t + 4];
            }
            unsigned bf[4][2];
#pragma unroll
            for (int ni = 0; ni < 4; ++ni) {
                int n0 = wn + ni*8;
                bf[ni][0] = B_[(k0 + t    )*136 + n0 + g];
                bf[ni][1] = B_[(k0 + t + 4)*136 + n0 + g];
            }
#pragma unroll
            for (int mi = 0; mi < 4; ++mi)
#pragma unroll
                for (int ni = 0; ni < 4; ++ni)
                    mma_tf32(acc[mi][ni], af[mi][0], af[mi][1], af[mi][2], af[mi][3],
                             bf[ni][0], bf[ni][1]);
        }
    }

#pragma unroll
    for (int ni = 0; ni < 4; ++ni) {
        int n = bn*128 + wn + ni*8 + 2*t;
        float2 bb = *reinterpret_cast<const float2*>(bp + n);
#pragma unroll
        for (int mi = 0; mi < 4; ++mi) {
            size_t m = (size_t)bm*128 + wm + mi*16;
            float2 v0, v1;
            v0.x = acc[mi][ni][0] + bb.x; v0.y = acc[mi][ni][1] + bb.y;
            v1.x = acc[mi][ni][2] + bb.x; v1.y = acc[mi][ni][3] + bb.y;
            *reinterpret_cast<float2*>(out + (m + g    )*EMB + n) = v0;
            *reinterpret_cast<float2*>(out + (m + g + 8)*EMB + n) = v1;
        }
    }
}

// ---------------------------------------------------------------------------
extern "C" void kernel_launch(void* const* d_in, const int* in_sizes, int n_in,
                              void* d_out, int out_size) {
    const float* x      = (const float*)d_in[0];
    const float* qkv_w  = (const float*)d_in[1];
    const float* qkv_b  = (const float*)d_in[2];
    const float* proj_w = (const float*)d_in[3];
    const float* proj_b = (const float*)d_in[4];
    const float* rpb    = (const float*)d_in[5];
    float* out = (float*)d_out;

    const int fused_smem = SMEM_FLOATS * 4;    // 73,344 B
    cudaFuncSetAttribute(fused_kernel, cudaFuncAttributeMaxDynamicSharedMemorySize, fused_smem);
    cudaFuncSetAttribute(proj_kernel,  cudaFuncAttributeMaxDynamicSharedMemorySize, PROJ_SMEM);

    bias_kernel<<<(NHEAD*WD*WD + 511)/512, 512>>>(rpb);
    wconv_kernel<<<(EMB*EMB + 511)/512, 512>>>(proj_w);
    fused_kernel<<<BNUM*NWIN*2, 256, fused_smem>>>(x, qkv_w, qkv_b);
    dim3 grid(BNUM*NTOK/128, EMB/128);
    proj_kernel<<<grid, 256, PROJ_SMEM>>>(proj_b, out);
}

// round 16
// speedup vs baseline: 1.0875x; 1.0875x over previous
#include <cuda_runtime.h>

// ---------------------------------------------------------------------------
// SWMSA: shifted-window multi-head self-attention (Swin block attention)
// B=32, H=W=56, WS=7, SS=3, NH=8, E=256, HD=32, NW=64, WD=49
// Kernel A : one-shot rel-pos-bias + shift-mask tables (4 window types)
// Kernel A2: one-shot proj_w -> tf32 pre-conversion
// Kernel B : tensor-core fused QKV + attention (R8 shape, x-loads hoisted,
//            epilogue stores tf32 bits into g_O)
// Kernel C : output projection GEMM, 2-stage cp.async pipeline (R13 form),
//            grid swapped so bn varies fastest -> A tile re-read hits L2
// ---------------------------------------------------------------------------

#define BNUM 32
#define HW   56
#define NHEAD 8
#define EMB  256
#define HDIM 32
#define NWIN 64
#define WD   49
#define NTOK (HW*HW)              // 3136

__device__ __align__(16) float    g_O  [(size_t)BNUM*NTOK*EMB];   // tf32 bits
__device__ __align__(16) float    g_BiM[4*NHEAD*WD*WD];           // 307KB, L2
__device__ __align__(16) unsigned g_Wp [EMB*EMB];                 // tf32 bits

// ---------------------------------------------------------------------------
__device__ __forceinline__ unsigned f2tf32(float f) {
    unsigned r;
    asm("cvt.rna.tf32.f32 %0, %1;" : "=r"(r) : "f"(f));
    return r;
}

__global__ __launch_bounds__(512) void bias_kernel(const float* __restrict__ rpb) {
    int i = blockIdx.x * 512 + threadIdx.x;
    if (i >= NHEAD*WD*WD) return;
    int h  = i / (WD*WD);
    int r2 = i - h*(WD*WD);
    int a  = r2 / WD;
    int bb = r2 - a*WD;
    int atr = a/7,  atc = a - 7*atr;
    int btr = bb/7, btc = bb - 7*btr;
    float bias = rpb[((atr - btr + 6)*13 + (atc - btc + 6))*NHEAD + h];
#pragma unroll
    for (int ty = 0; ty < 4; ++ty) {
        int Rw = ty >> 1, Cw = ty & 1;
        int ra = (Rw ? (atr<4?1:2) : 0)*3 + (Cw ? (atc<4?1:2) : 0);
        int rb = (Rw ? (btr<4?1:2) : 0)*3 + (Cw ? (btc<4?1:2) : 0);
        g_BiM[ty*(NHEAD*WD*WD) + i] = bias + ((ra == rb) ? 0.f : -100.f);
    }
}

__global__ __launch_bounds__(512) void wconv_kernel(const float* __restrict__ Wp) {
    int i = blockIdx.x * 512 + threadIdx.x;
    if (i < EMB*EMB) g_Wp[i] = f2tf32(Wp[i]);
}

// ---------------------------------------------------------------------------
__device__ __forceinline__ void mma_tf32(float* c, unsigned a0, unsigned a1,
                                         unsigned a2, unsigned a3,
                                         unsigned b0, unsigned b1) {
    asm volatile(
        "mma.sync.aligned.m16n8k8.row.col.f32.tf32.tf32.f32 "
        "{%0,%1,%2,%3}, {%4,%5,%6,%7}, {%8,%9}, {%0,%1,%2,%3};\n"
        : "+f"(c[0]), "+f"(c[1]), "+f"(c[2]), "+f"(c[3])
        : "r"(a0), "r"(a1), "r"(a2), "r"(a3), "r"(b0), "r"(b1));
}

__device__ __forceinline__ void cp_async16(unsigned smem_addr, const void* gptr) {
    asm volatile("cp.async.ca.shared.global [%0], [%1], 16;\n"
                 :: "r"(smem_addr), "l"(gptr));
}
#define CP_COMMIT() asm volatile("cp.async.commit_group;\n" ::: "memory")
#define CP_WAIT0()  asm volatile("cp.async.wait_group 0;\n" ::: "memory")

// ---------------------------------------------------------------------------
// Fused kernel smem layout (floats), block = (window, 4 heads)  [R8 shape]:
//   Ks @ 0     : 4 heads x 32 d x 56 j (tf32)            = 7168
//   Vs @ 7168  : 4 heads x 32 d x 60 j (tf32, zeroed)    = 7680
//   Ws @ 14848 : 32 k x stride 104 (tf32)                = 3328
//   bs @ 18176 : 96 (fp32)
//   gof@ 18272 : 64 ints
//   total 18336 floats = 73,344 B  -> 2 blocks/SM
// ---------------------------------------------------------------------------
#define OFF_KS 0
#define KS_H   1792
#define OFF_VS 7168
#define VS_H   1920
#define OFF_WS 14848
#define WS_S   104
#define OFF_BS 18176
#define OFF_GO 18272
#define SMEM_FLOATS 18336

__global__ __launch_bounds__(256, 2) void fused_kernel(const float* __restrict__ x,
                                                       const float* __restrict__ Wq,
                                                       const float* __restrict__ bq) {
    extern __shared__ float sm[];
    float* bs  = sm + OFF_BS;
    int*   gof = reinterpret_cast<int*>(sm + OFF_GO);
    unsigned* Wsu = reinterpret_cast<unsigned*>(sm + OFF_WS);

    int bw2 = blockIdx.x;
    int hg = bw2 & 1, bw = bw2 >> 1;
    int b  = bw >> 6, w = bw & 63;
    int wr = w >> 3,  wc = w & 7;
    int tid = threadIdx.x, warp = tid >> 5, lane = tid & 31;
    int g = lane >> 2, t = lane & 3;
    int lh = warp >> 1, p = warp & 1;
    int h = hg*4 + lh;
    int m0_0 = p ? 17 : 0;
    int m0_1 = p ? 33 : 16;
    int hc = h*HDIM;

    // ---- issue A-frag loads FIRST (hidden behind staging below) ----
    auto rowoff = [&](int i) {
        int tr = i/7, tc = i - 7*tr;
        int row = wr*7 + tr + 3; if (row >= HW) row -= HW;
        int col = wc*7 + tc + 3; if (col >= HW) col -= HW;
        return (b*NTOK + row*HW + col)*EMB + hc;
    };
    float av[2][4][4];
    {
        int o00 = rowoff(m0_0 + g), o01 = rowoff(m0_0 + g + 8);
        int o10 = rowoff(m0_1 + g), o11 = rowoff(m0_1 + g + 8);
#pragma unroll
        for (int ks = 0; ks < 4; ++ks) {
            int k0 = ks*8;
            av[0][ks][0] = __ldg(x + o00 + k0 + t    );
            av[0][ks][1] = __ldg(x + o01 + k0 + t    );
            av[0][ks][2] = __ldg(x + o00 + k0 + t + 4);
            av[0][ks][3] = __ldg(x + o01 + k0 + t + 4);
            av[1][ks][0] = __ldg(x + o10 + k0 + t    );
            av[1][ks][1] = __ldg(x + o11 + k0 + t    );
            av[1][ks][2] = __ldg(x + o10 + k0 + t + 4);
            av[1][ks][3] = __ldg(x + o11 + k0 + t + 4);
        }
    }

    // ---- staging (overlaps the LDGs above) ----
    {
        float4* z = reinterpret_cast<float4*>(sm + OFF_VS);
        for (int i = tid; i < 7680/4; i += 256) z[i] = make_float4(0,0,0,0);
    }
    for (int i = tid; i < 32*96; i += 256) {
        int k = i / 96, n = i - k*96;
        Wsu[k*WS_S + n] = f2tf32(Wq[i]);
    }
    if (tid < 96) bs[tid] = bq[tid];
    if (tid < WD) {
        int tr = tid/7, tc = tid - 7*tr;
        int row = wr*7 + tr + 3; if (row >= HW) row -= HW;
        int col = wc*7 + tc + 3; if (col >= HW) col -= HW;
        gof[tid] = (b*NTOK + row*HW + col)*EMB;
    }
    __syncthreads();

    // convert A-frags to tf32
    unsigned a_[2][4][4];
#pragma unroll
    for (int mi = 0; mi < 2; ++mi)
#pragma unroll
        for (int ks = 0; ks < 4; ++ks)
#pragma unroll
            for (int i = 0; i < 4; ++i)
                a_[mi][ks][i] = f2tf32(av[mi][ks][i]);

    // ---- Q pass (cols 0..31) -> frags (scaled, tf32) ----
    unsigned qu[2][4][4];
    const float qscale = 0.17677669529663687f;
#pragma unroll
    for (int mi = 0; mi < 2; ++mi) {
#pragma unroll
        for (int nt = 0; nt < 4; ++nt) {
            float c4[4] = {0.f,0.f,0.f,0.f};
#pragma unroll
            for (int ks = 0; ks < 4; ++ks) {
                int k0 = ks*8;
                unsigned b0 = Wsu[(k0+t  )*WS_S + nt*8 + g];
                unsigned b1 = Wsu[(k0+t+4)*WS_S + nt*8 + g];
                mma_tf32(c4, a_[mi][ks][0],a_[mi][ks][1],a_[mi][ks][2],a_[mi][ks][3], b0,b1);
            }
            int d0 = nt*8 + 2*t;
            qu[mi][nt][0] = f2tf32((c4[0] + bs[d0  ]) * qscale);
            qu[mi][nt][1] = f2tf32((c4[1] + bs[d0+1]) * qscale);
            qu[mi][nt][2] = f2tf32((c4[2] + bs[d0  ]) * qscale);
            qu[mi][nt][3] = f2tf32((c4[3] + bs[d0+1]) * qscale);
        }
    }
    // ---- K pass (cols 32..63) -> Ks[d][j] stride 56 ----
    {
        unsigned* Kh = reinterpret_cast<unsigned*>(sm + OFF_KS) + lh*KS_H;
#pragma unroll
        for (int mi = 0; mi < 2; ++mi) {
            int m0 = mi ? m0_1 : m0_0;
#pragma unroll
            for (int nt = 0; nt < 4; ++nt) {
                float c4[4] = {0.f,0.f,0.f,0.f};
#pragma unroll
                for (int ks = 0; ks < 4; ++ks) {
                    int k0 = ks*8;
                    unsigned b0 = Wsu[(k0+t  )*WS_S + 32 + nt*8 + g];
                    unsigned b1 = Wsu[(k0+t+4)*WS_S + 32 + nt*8 + g];
                    mma_tf32(c4, a_[mi][ks][0],a_[mi][ks][1],a_[mi][ks][2],a_[mi][ks][3], b0,b1);
                }
                int d0 = nt*8 + 2*t;
                Kh[(d0  )*56 + m0+g  ] = f2tf32(c4[0] + bs[32+d0  ]);
                Kh[(d0+1)*56 + m0+g  ] = f2tf32(c4[1] + bs[32+d0+1]);
                Kh[(d0  )*56 + m0+g+8] = f2tf32(c4[2] + bs[32+d0  ]);
                Kh[(d0+1)*56 + m0+g+8] = f2tf32(c4[3] + bs[32+d0+1]);
            }
        }
    }
    // ---- V pass (cols 64..95) -> Vs[d][j] stride 60 (transposed) ----
    {
        unsigned* Vh = reinterpret_cast<unsigned*>(sm + OFF_VS) + lh*VS_H;
#pragma unroll
        for (int mi = 0; mi < 2; ++mi) {
            int m0 = mi ? m0_1 : m0_0;
#pragma unroll
            for (int nt = 0; nt < 4; ++nt) {
                float c4[4] = {0.f,0.f,0.f,0.f};
#pragma unroll
                for (int ks = 0; ks < 4; ++ks) {
                    int k0 = ks*8;
                    unsigned b0 = Wsu[(k0+t  )*WS_S + 64 + nt*8 + g];
                    unsigned b1 = Wsu[(k0+t+4)*WS_S + 64 + nt*8 + g];
                    mma_tf32(c4, a_[mi][ks][0],a_[mi][ks][1],a_[mi][ks][2],a_[mi][ks][3], b0,b1);
                }
                int d0 = nt*8 + 2*t;
                Vh[(d0  )*60 + m0+g  ] = f2tf32(c4[0] + bs[64+d0  ]);
                Vh[(d0+1)*60 + m0+g  ] = f2tf32(c4[1] + bs[64+d0+1]);
                Vh[(d0  )*60 + m0+g+8] = f2tf32(c4[2] + bs[64+d0  ]);
                Vh[(d0+1)*60 + m0+g+8] = f2tf32(c4[3] + bs[64+d0+1]);
            }
        }
    }

    // rearrange Q c-frags -> a-frags via warp shuffles
    int src0 = (g << 2) | (t >> 1);
    unsigned qa[2][4][4];
#pragma unroll
    for (int mi = 0; mi < 2; ++mi)
#pragma unroll
        for (int ks = 0; ks < 4; ++ks) {
            unsigned v00 = __shfl_sync(0xffffffffu, qu[mi][ks][0], src0);
            unsigned v01 = __shfl_sync(0xffffffffu, qu[mi][ks][1], src0);
            unsigned v02 = __shfl_sync(0xffffffffu, qu[mi][ks][2], src0);
            unsigned v03 = __shfl_sync(0xffffffffu, qu[mi][ks][3], src0);
            unsigned v10 = __shfl_sync(0xffffffffu, qu[mi][ks][0], src0+2);
            unsigned v11 = __shfl_sync(0xffffffffu, qu[mi][ks][1], src0+2);
            unsigned v12 = __shfl_sync(0xffffffffu, qu[mi][ks][2], src0+2);
            unsigned v13 = __shfl_sync(0xffffffffu, qu[mi][ks][3], src0+2);
            bool odd = (t & 1);
            qa[mi][ks][0] = odd ? v01 : v00;
            qa[mi][ks][1] = odd ? v03 : v02;
            qa[mi][ks][2] = odd ? v11 : v10;
            qa[mi][ks][3] = odd ? v13 : v12;
        }

    __syncthreads();

    // ---- scores: S = Q · K^T ----
    float s[2][7][4];
#pragma unroll
    for (int mi = 0; mi < 2; ++mi)
#pragma unroll
        for (int nt = 0; nt < 7; ++nt)
            s[mi][nt][0]=s[mi][nt][1]=s[mi][nt][2]=s[mi][nt][3]=0.f;
    {
        const unsigned* Kh = reinterpret_cast<const unsigned*>(sm + OFF_KS) + lh*KS_H;
#pragma unroll
        for (int ks = 0; ks < 4; ++ks) {
            int k0 = ks*8;
#pragma unroll
            for (int nt = 0; nt < 7; ++nt) {
                unsigned b0 = Kh[(k0+t  )*56 + nt*8 + g];
                unsigned b1 = Kh[(k0+t+4)*56 + nt*8 + g];
                mma_tf32(s[0][nt], qa[0][ks][0],qa[0][ks][1],qa[0][ks][2],qa[0][ks][3], b0,b1);
                mma_tf32(s[1][nt], qa[1][ks][0],qa[1][ks][1],qa[1][ks][2],qa[1][ks][3], b0,b1);
            }
        }
    }

    // ---- softmax (bias+mask precombined per window type) ----
    int ty = ((wr == 7) ? 2 : 0) + ((wc == 7) ? 1 : 0);
    const float* Bh = g_BiM + (ty*NHEAD + h)*(WD*WD);
    int row0[2] = {m0_0 + g, m0_1 + g};
    float inv_l[2][2];
#pragma unroll
    for (int mi = 0; mi < 2; ++mi) {
#pragma unroll
        for (int half = 0; half < 2; ++half) {
            int i = row0[mi] + half*8;
            const float* Br = Bh + i*WD;
            float mx = -1e30f;
#pragma unroll
            for (int nt = 0; nt < 7; ++nt) {
#pragma unroll
                for (int c = 0; c < 2; ++c) {
                    int j = nt*8 + 2*t + c;
                    float v = (j < WD) ? s[mi][nt][half*2+c] + __ldg(Br + j) : -1e30f;
                    s[mi][nt][half*2+c] = v;
                    mx = fmaxf(mx, v);
                }
            }
            mx = fmaxf(mx, __shfl_xor_sync(0xffffffffu, mx, 1));
            mx = fmaxf(mx, __shfl_xor_sync(0xffffffffu, mx, 2));
            float l = 0.f;
#pragma unroll
            for (int nt = 0; nt < 7; ++nt)
#pragma unroll
                for (int c = 0; c < 2; ++c) {
                    float e = __expf(s[mi][nt][half*2+c] - mx);
                    s[mi][nt][half*2+c] = e;
                    l += e;
                }
            l += __shfl_xor_sync(0xffffffffu, l, 1);
            l += __shfl_xor_sync(0xffffffffu, l, 2);
            inv_l[mi][half] = 1.f / l;
        }
    }
#pragma unroll
    for (int mi = 0; mi < 2; ++mi)
#pragma unroll
        for (int nt = 0; nt < 7; ++nt)
#pragma unroll
            for (int c = 0; c < 4; ++c)
                s[mi][nt][c] = __uint_as_float(f2tf32(s[mi][nt][c]));

    // ---- PV: O = P · V ----
    float o[2][4][4];
#pragma unroll
    for (int mi = 0; mi < 2; ++mi)
#pragma unroll
        for (int nt = 0; nt < 4; ++nt)
            o[mi][nt][0]=o[mi][nt][1]=o[mi][nt][2]=o[mi][nt][3]=0.f;
    {
        const unsigned* Vh = reinterpret_cast<const unsigned*>(sm + OFF_VS) + lh*VS_H;
#pragma unroll
        for (int ks = 0; ks < 7; ++ks) {
            int k0 = ks*8;
            unsigned pa[2][4];
#pragma unroll
            for (int mi = 0; mi < 2; ++mi) {
                float v00 = __shfl_sync(0xffffffffu, s[mi][ks][0], src0);
                float v01 = __shfl_sync(0xffffffffu, s[mi][ks][1], src0);
                float v02 = __shfl_sync(0xffffffffu, s[mi][ks][2], src0);
                float v03 = __shfl_sync(0xffffffffu, s[mi][ks][3], src0);
                float v10 = __shfl_sync(0xffffffffu, s[mi][ks][0], src0+2);
                float v11 = __shfl_sync(0xffffffffu, s[mi][ks][1], src0+2);
                float v12 = __shfl_sync(0xffffffffu, s[mi][ks][2], src0+2);
                float v13 = __shfl_sync(0xffffffffu, s[mi][ks][3], src0+2);
                bool odd = (t & 1);
                pa[mi][0] = __float_as_uint(odd ? v01 : v00);
                pa[mi][1] = __float_as_uint(odd ? v03 : v02);
                pa[mi][2] = __float_as_uint(odd ? v11 : v10);
                pa[mi][3] = __float_as_uint(odd ? v13 : v12);
            }
#pragma unroll
            for (int nt = 0; nt < 4; ++nt) {
                unsigned b0 = Vh[(nt*8+g)*60 + k0+t  ];
                unsigned b1 = Vh[(nt*8+g)*60 + k0+t+4];
                mma_tf32(o[0][nt], pa[0][0],pa[0][1],pa[0][2],pa[0][3], b0,b1);
                mma_tf32(o[1][nt], pa[1][0],pa[1][1],pa[1][2],pa[1][3], b0,b1);
            }
        }
    }

    // ---- scatter output as tf32 bits (exactly what proj would convert) ----
#pragma unroll
    for (int mi = 0; mi < 2; ++mi)
#pragma unroll
        for (int half = 0; half < 2; ++half) {
            int i = row0[mi] + half*8;
            float inv = inv_l[mi][half];
            float* dst = g_O + gof[i] + hc;
#pragma unroll
            for (int nt = 0; nt < 4; ++nt) {
                float2 v;
                v.x = __uint_as_float(f2tf32(o[mi][nt][half*2+0] * inv));
                v.y = __uint_as_float(f2tf32(o[mi][nt][half*2+1] * inv));
                *reinterpret_cast<float2*>(dst + nt*8 + 2*t) = v;
            }
        }
}

// ---------------------------------------------------------------------------
// Kernel C: output projection GEMM (R13 2-stage pipeline). A (g_O) and B
// (g_Wp) already tf32 bits; staging is raw cp.async, double-buffered.
// Grid: bn = blockIdx.x (fastest) so both bn-blocks of a bm launch adjacent
// -> second read of the A tile hits L2 instead of DRAM.
// ---------------------------------------------------------------------------
#define PA_SZ (128*36)       // 4608 words per A buffer
#define PB_SZ (32*136)       // 4352 words per B buffer
#define PROJ_SMEM ((2*PA_SZ + 2*PB_SZ)*4)   // 71,680 B

__device__ __forceinline__ void proj_stage(int kb, unsigned* Ab, unsigned* Bb,
                                           const float* Ag, const unsigned* Wg,
                                           int tid, int bn) {
    int ar = tid >> 1, ac = (tid & 1) * 16;
    unsigned ad = (unsigned)__cvta_generic_to_shared(Ab + ar*36 + ac);
    const float* asrc = Ag + ar*EMB + kb*32 + ac;
#pragma unroll
    for (int i = 0; i < 4; ++i) cp_async16(ad + i*16, asrc + i*4);
    int br = tid >> 3, bc = (tid & 7) * 16;
    unsigned bd = (unsigned)__cvta_generic_to_shared(Bb + br*136 + bc);
    const unsigned* bsrc = Wg + (kb*32 + br)*EMB + bn*128 + bc;
#pragma unroll
    for (int i = 0; i < 4; ++i) cp_async16(bd + i*16, bsrc + i*4);
}

__global__ __launch_bounds__(256) void proj_kernel(const float* __restrict__ bp,
                                                   float* __restrict__ out) {
    extern __shared__ unsigned psm[];
    unsigned* Ab[2] = {psm, psm + PA_SZ};
    unsigned* Bb[2] = {psm + 2*PA_SZ, psm + 2*PA_SZ + PB_SZ};

    int bn = blockIdx.x;               // fastest dim -> L2 reuse of A
    int bm = blockIdx.y;
    int tid = threadIdx.x;
    int warp = tid >> 5, lane = tid & 31;
    int g = lane >> 2, t = lane & 3;
    int wm = (warp & 1) * 64;
    int wn = (warp >> 1) * 32;

    float acc[4][4][4];
#pragma unroll
    for (int mi = 0; mi < 4; ++mi)
#pragma unroll
        for (int ni = 0; ni < 4; ++ni)
#pragma unroll
            for (int rr = 0; rr < 4; ++rr) acc[mi][ni][rr] = 0.f;

    const float* Ag = g_O + (size_t)bm * 128 * EMB;

    proj_stage(0, Ab[0], Bb[0], Ag, g_Wp, tid, bn);
    CP_COMMIT();
    CP_WAIT0();
    __syncthreads();

#pragma unroll 1
    for (int kb = 0; kb < 8; ++kb) {
        int cur = kb & 1;
        if (kb < 7) {
            proj_stage(kb + 1, Ab[cur^1], Bb[cur^1], Ag, g_Wp, tid, bn);
            CP_COMMIT();
        }
        const unsigned* A_ = Ab[cur];
        const unsigned* B_ = Bb[cur];
#pragma unroll
        for (int ks = 0; ks < 4; ++ks) {
            int k0 = ks * 8;
            unsigned af[4][4];
#pragma unroll
            for (int mi = 0; mi < 4; ++mi) {
                int m0 = wm + mi*16;
                af[mi][0] = A_[(m0 + g    )*36 + k0 + t    ];
                af[mi][1] = A_[(m0 + g + 8)*36 + k0 + t    ];
                af[mi][2] = A_[(m0 + g    )*36 + k0 + t + 4];
                af[mi][3] = A_[(m0 + g + 8)*36 + k0 + t + 4];
            }
            unsigned bf[4][2];
#pragma unroll
            for (int ni = 0; ni < 4; ++ni) {
                int n0 = wn + ni*8;
                bf[ni][0] = B_[(k0 + t    )*136 + n0 + g];
                bf[ni][1] = B_[(k0 + t + 4)*136 + n0 + g];
            }
#pragma unroll
            for (int mi = 0; mi < 4; ++mi)
#pragma unroll
                for (int ni = 0; ni < 4; ++ni)
                    mma_tf32(acc[mi][ni], af[mi][0], af[mi][1], af[mi][2], af[mi][3],
                             bf[ni][0], bf[ni][1]);
        }
        if (kb < 7) {
            CP_WAIT0();
            __syncthreads();
        }
    }

#pragma unroll
    for (int ni = 0; ni < 4; ++ni) {
        int n = bn*128 + wn + ni*8 + 2*t;
        float2 bb = *reinterpret_cast<const float2*>(bp + n);
#pragma unroll
        for (int mi = 0; mi < 4; ++mi) {
            size_t m = (size_t)bm*128 + wm + mi*16;
            float2 v0, v1;
            v0.x = acc[mi][ni][0] + bb.x; v0.y = acc[mi][ni][1] + bb.y;
            v1.x = acc[mi][ni][2] + bb.x; v1.y = acc[mi][ni][3] + bb.y;
            *reinterpret_cast<float2*>(out + (m + g    )*EMB + n) = v0;
            *reinterpret_cast<float2*>(out + (m + g + 8)*EMB + n) = v1;
        }
    }
}

// ---------------------------------------------------------------------------
extern "C" void kernel_launch(void* const* d_in, const int* in_sizes, int n_in,
                              void* d_out, int out_size) {
    const float* x      = (const float*)d_in[0];
    const float* qkv_w  = (const float*)d_in[1];
    const float* qkv_b  = (const float*)d_in[2];
    const float* proj_w = (const float*)d_in[3];
    const float* proj_b = (const float*)d_in[4];
    const float* rpb    = (const float*)d_in[5];
    float* out = (float*)d_out;

    const int fused_smem = SMEM_FLOATS * 4;    // 73,344 B
    cudaFuncSetAttribute(fused_kernel, cudaFuncAttributeMaxDynamicSharedMemorySize, fused_smem);
    cudaFuncSetAttribute(proj_kernel,  cudaFuncAttributeMaxDynamicSharedMemorySize, PROJ_SMEM);

    bias_kernel<<<(NHEAD*WD*WD + 511)/512, 512>>>(rpb);
    wconv_kernel<<<(EMB*EMB + 511)/512, 512>>>(proj_w);
    fused_kernel<<<BNUM*NWIN*2, 256, fused_smem>>>(x, qkv_w, qkv_b);
    dim3 grid(EMB/128, BNUM*NTOK/128);        // bn fastest -> A L2 reuse
    proj_kernel<<<grid, 256, PROJ_SMEM>>>(proj_b, out);
}